// round 9
// baseline (speedup 1.0000x reference)
#include <cuda_runtime.h>
#include <float.h>

// ROI max pool, four-phase (each phase individually measured-fast):
//  1) transpose: [2,256,50,50] -> channel-last g_feat_t [2,50,50,256], float4
//  2) prep: per-(roi,bin) bounds -> g_meta (keeps pool at 32 regs / full occ)
//  3) pool: 6272 blocks x 64 thr; warp = bin x 128 ch; float4 LDG (MLP<=8),
//     float4 coalesced store to bin-major g_tmp[n][ij][c]
//  4) reshape: g_tmp[n][ij][c] -> out[n][c][ij]; 1024 blocks, float4 reads,
//     smem transpose, coalesced writes

#define OUTP 7
#define NBINS 49
#define CCH  256
#define HH   50
#define WW   50
#define HWSZ (HH * WW)
#define BB   2
#define CS   (CCH / 4)

__device__ __align__(16) float g_feat_t[BB * HWSZ * CCH];   // 5.12 MB
__device__ __align__(16) float g_tmp[128 * NBINS * CCH];    // 6.42 MB
__device__ int4 g_meta[128 * NBINS];

// ---------------- 1) transpose (float4 both sides) ----------------
__global__ __launch_bounds__(256) void transpose_kernel(const float* __restrict__ feat)
{
    __shared__ float tile[32][33];
    int b   = blockIdx.z;
    int hw0 = blockIdx.x * 32;
    int c0  = blockIdx.y * 32;
    int t   = threadIdx.x;

    {
        int cl = t >> 3;
        int h4 = (t & 7) * 4;
        int hw = hw0 + h4;
        if (hw < HWSZ) {
            float4 v = __ldg((const float4*)
                (feat + ((size_t)b * CCH + c0 + cl) * HWSZ + hw));
            tile[cl][h4 + 0] = v.x;
            tile[cl][h4 + 1] = v.y;
            tile[cl][h4 + 2] = v.z;
            tile[cl][h4 + 3] = v.w;
        }
    }
    __syncthreads();
    {
        int hwl = t >> 3;
        int c4  = (t & 7) * 4;
        int hw  = hw0 + hwl;
        if (hw < HWSZ) {
            float4 o;
            o.x = tile[c4 + 0][hwl];
            o.y = tile[c4 + 1][hwl];
            o.z = tile[c4 + 2][hwl];
            o.w = tile[c4 + 3][hwl];
            *(float4*)(g_feat_t + ((size_t)b * HWSZ + hw) * CCH + c0 + c4) = o;
        }
    }
}

// ---------------- 2) prep ----------------
__global__ void prep_kernel(const float* __restrict__ rois)
{
    int t = blockIdx.x * blockDim.x + threadIdx.x;
    if (t >= 128 * NBINS) return;
    int n  = t / NBINS;
    int ij = t - n * NBINS;
    int i  = ij / OUTP;
    int j  = ij - i * OUTP;

    const float* r = rois + n * 5;
    int im = (int)rintf(r[0]);
    int x1 = (int)rintf(r[1] * 0.0625f);
    int y1 = (int)rintf(r[2] * 0.0625f);
    int x2 = (int)rintf(r[3] * 0.0625f);
    int y2 = (int)rintf(r[4] * 0.0625f);
    unsigned h = (unsigned)(y2 - y1 + 1);
    unsigned w = (unsigned)(x2 - x1 + 1);

    int ys = (int)((unsigned)(i * h) / 7u) + y1;
    int ye = (int)(((unsigned)((i + 1) * h) + 6u) / 7u) + y1;
    int xs = (int)((unsigned)(j * w) / 7u) + x1;
    int xe = (int)(((unsigned)((j + 1) * w) + 6u) / 7u) + x1;
    ye = min(ye, HH);  xe = min(xe, WW);

    int4 m;
    m.x = im * HWSZ + ys * WW + xs;
    m.y = ye - ys;
    m.z = xe - xs - 1;
    m.w = 0;
    g_meta[t] = m;
}

__device__ __forceinline__ float4 fmax4(float4 a, float4 b)
{
    return make_float4(fmaxf(a.x, b.x), fmaxf(a.y, b.y),
                       fmaxf(a.z, b.z), fmaxf(a.w, b.w));
}

// ---------------- 3) pool: 6272 blocks x 64 threads ----------------
__global__ __launch_bounds__(64) void roi_pool_kernel(void)
{
    int task = blockIdx.x;            // n*NBINS + ij
    int lane = threadIdx.x & 31;
    int cg   = threadIdx.x >> 5;

    int4 m = __ldg(&g_meta[task]);
    int wm1 = m.z;

    const float4* base = (const float4*)g_feat_t
                       + (size_t)m.x * CS + cg * 32 + lane;

    float4 acc = make_float4(-FLT_MAX, -FLT_MAX, -FLT_MAX, -FLT_MAX);
    for (int r = 0; r < m.y; ++r) {
        const float4* row = base + (size_t)r * (WW * CS);
        float4 v0 = __ldg(row);
        float4 v1 = __ldg(row + min(1, wm1) * CS);
        float4 v2 = __ldg(row + min(2, wm1) * CS);
        float4 v3 = __ldg(row + min(3, wm1) * CS);
        float4 m0 = fmax4(v0, v1);
        float4 m1 = fmax4(v2, v3);
        if (wm1 >= 4) {
            float4 v4 = __ldg(row + 4 * CS);
            float4 v5 = __ldg(row + min(5, wm1) * CS);
            float4 v6 = __ldg(row + min(6, wm1) * CS);
            float4 v7 = __ldg(row + min(7, wm1) * CS);
            m0 = fmax4(m0, fmax4(v4, v5));
            m1 = fmax4(m1, fmax4(v6, v7));
        }
        acc = fmax4(acc, fmax4(m0, m1));
    }

    ((float4*)g_tmp)[(size_t)task * (CCH / 4) + cg * 32 + lane] = acc;
}

// ---------------- 4) reshape: g_tmp[n][ij][c] -> out[n][c][ij] -------------
// grid (8, 128): 32-channel slab per block; 256 threads; float4 reads
__global__ __launch_bounds__(256) void reshape_kernel(float* __restrict__ out)
{
    __shared__ float s[NBINS][33];
    int c0 = blockIdx.x * 32;
    int n  = blockIdx.y;
    int t  = threadIdx.x;

    // read: 49 rows x 8 float4 = 392 float4
    const float4* src4 = (const float4*)(g_tmp + (size_t)n * NBINS * CCH + c0);
    for (int p = t; p < NBINS * 8; p += 256) {
        int ij = p >> 3;
        int q  = p & 7;
        float4 v = __ldg(src4 + (size_t)ij * (CCH / 4) + q);
        s[ij][q * 4 + 0] = v.x;
        s[ij][q * 4 + 1] = v.y;
        s[ij][q * 4 + 2] = v.z;
        s[ij][q * 4 + 3] = v.w;
    }
    __syncthreads();

    // write: 32 channels x 49 bins, runs of 49 contiguous floats
    float* dst = out + ((size_t)n * CCH + c0) * NBINS;
    for (int p = t; p < 32 * NBINS; p += 256) {
        int c  = p / NBINS;
        int ij = p - c * NBINS;
        dst[p] = s[ij][c];
    }
}

extern "C" void kernel_launch(void* const* d_in, const int* in_sizes, int n_in,
                              void* d_out, int out_size)
{
    const float* feat = (const float*)d_in[0];
    const float* rois = (const float*)d_in[1];
    float* out = (float*)d_out;

    dim3 tgrid((HWSZ + 31) / 32, CCH / 32, BB);
    transpose_kernel<<<tgrid, 256>>>(feat);

    prep_kernel<<<(128 * NBINS + 255) / 256, 256>>>(rois);

    roi_pool_kernel<<<128 * NBINS, 64>>>();

    reshape_kernel<<<dim3(8, 128), 256>>>(out);
}

// round 10
// speedup vs baseline: 1.0152x; 1.0152x over previous
#include <cuda_runtime.h>
#include <float.h>

// ROI max pool, three-phase, no output scratch:
//  1) transpose: [2,256,50,50] -> channel-last g_feat_t [2,50,50,256], float4
//  2) prep: per-(roi,bin) bounds -> g_meta (keeps pool regs low)
//  3) pool: block = (roi, bin-quad, 128-ch group), 4 warps = 4 consecutive ij
//     bins; smem-staged (conflict-free pitch 136) and written directly to
//     out[n][c][ij] as 16B runs (~8 lines per warp-store, no divides).

#define OUTP 7
#define NBINS 49
#define CCH  256
#define HH   50
#define WW   50
#define HWSZ (HH * WW)
#define BB   2
#define CS   (CCH / 4)

__device__ __align__(16) float g_feat_t[BB * HWSZ * CCH];   // 5.12 MB
__device__ int4 g_meta[128 * NBINS];

// ---------------- 1) transpose (float4 both sides) ----------------
__global__ __launch_bounds__(256) void transpose_kernel(const float* __restrict__ feat)
{
    __shared__ float tile[32][33];
    int b   = blockIdx.z;
    int hw0 = blockIdx.x * 32;
    int c0  = blockIdx.y * 32;
    int t   = threadIdx.x;

    {
        int cl = t >> 3;
        int h4 = (t & 7) * 4;
        int hw = hw0 + h4;
        if (hw < HWSZ) {
            float4 v = __ldg((const float4*)
                (feat + ((size_t)b * CCH + c0 + cl) * HWSZ + hw));
            tile[cl][h4 + 0] = v.x;
            tile[cl][h4 + 1] = v.y;
            tile[cl][h4 + 2] = v.z;
            tile[cl][h4 + 3] = v.w;
        }
    }
    __syncthreads();
    {
        int hwl = t >> 3;
        int c4  = (t & 7) * 4;
        int hw  = hw0 + hwl;
        if (hw < HWSZ) {
            float4 o;
            o.x = tile[c4 + 0][hwl];
            o.y = tile[c4 + 1][hwl];
            o.z = tile[c4 + 2][hwl];
            o.w = tile[c4 + 3][hwl];
            *(float4*)(g_feat_t + ((size_t)b * HWSZ + hw) * CCH + c0 + c4) = o;
        }
    }
}

// ---------------- 2) prep ----------------
__global__ void prep_kernel(const float* __restrict__ rois)
{
    int t = blockIdx.x * blockDim.x + threadIdx.x;
    if (t >= 128 * NBINS) return;
    int n  = t / NBINS;
    int ij = t - n * NBINS;
    int i  = ij / OUTP;
    int j  = ij - i * OUTP;

    const float* r = rois + n * 5;
    int im = (int)rintf(r[0]);
    int x1 = (int)rintf(r[1] * 0.0625f);
    int y1 = (int)rintf(r[2] * 0.0625f);
    int x2 = (int)rintf(r[3] * 0.0625f);
    int y2 = (int)rintf(r[4] * 0.0625f);
    unsigned h = (unsigned)(y2 - y1 + 1);
    unsigned w = (unsigned)(x2 - x1 + 1);

    int ys = (int)((unsigned)(i * h) / 7u) + y1;
    int ye = (int)(((unsigned)((i + 1) * h) + 6u) / 7u) + y1;
    int xs = (int)((unsigned)(j * w) / 7u) + x1;
    int xe = (int)(((unsigned)((j + 1) * w) + 6u) / 7u) + x1;
    ye = min(ye, HH);  xe = min(xe, WW);

    int4 m;
    m.x = im * HWSZ + ys * WW + xs;
    m.y = ye - ys;
    m.z = xe - xs - 1;
    m.w = 0;
    g_meta[t] = m;
}

__device__ __forceinline__ float4 fmax4(float4 a, float4 b)
{
    return make_float4(fmaxf(a.x, b.x), fmaxf(a.y, b.y),
                       fmaxf(a.z, b.z), fmaxf(a.w, b.w));
}

// ---------------- 3) fused pool + output ----------------
// grid: x = 13 quads * 2 cg = 26, y = 128 rois; block: 128 thr = 4 warps.
#define SPITCH 136   // bank(dj,c) = (8*dj + c) mod 32 -> conflict-free
__global__ __launch_bounds__(128) void roi_pool_kernel(float* __restrict__ out)
{
    __shared__ __align__(16) float s[4 * SPITCH];

    int q    = blockIdx.x >> 1;        // bin quad: bins 4q .. 4q+3
    int cg   = blockIdx.x & 1;         // channels [cg*128, +128)
    int n    = blockIdx.y;
    int lane = threadIdx.x & 31;
    int wrp  = threadIdx.x >> 5;       // 0..3 -> bin 4q+wrp
    int ij   = 4 * q + wrp;

    float4 acc = make_float4(-FLT_MAX, -FLT_MAX, -FLT_MAX, -FLT_MAX);
    if (ij < NBINS) {
        int4 m = __ldg(&g_meta[n * NBINS + ij]);
        int wm1 = m.z;
        const float4* base = (const float4*)g_feat_t
                           + (size_t)m.x * CS + cg * 32 + lane;
        for (int r = 0; r < m.y; ++r) {
            const float4* row = base + (size_t)r * (WW * CS);
            float4 v0 = __ldg(row);
            float4 v1 = __ldg(row + min(1, wm1) * CS);
            float4 v2 = __ldg(row + min(2, wm1) * CS);
            float4 v3 = __ldg(row + min(3, wm1) * CS);
            float4 m0 = fmax4(v0, v1);
            float4 m1 = fmax4(v2, v3);
            if (wm1 >= 4) {            // warp-uniform branch
                float4 v4 = __ldg(row + 4 * CS);
                float4 v5 = __ldg(row + min(5, wm1) * CS);
                float4 v6 = __ldg(row + min(6, wm1) * CS);
                float4 v7 = __ldg(row + min(7, wm1) * CS);
                m0 = fmax4(m0, fmax4(v4, v5));
                m1 = fmax4(m1, fmax4(v6, v7));
            }
            acc = fmax4(acc, fmax4(m0, m1));
        }
    }
    *(float4*)&s[wrp * SPITCH + lane * 4] = acc;
    __syncthreads();

    // write out[n][cg*128 + c][4q + dj]; shift/and index math only
    float* dst = out + ((size_t)n * CCH + cg * 128) * NBINS + 4 * q;
    if (q < 12) {
        // 128 ch x 4 bins = 512 floats; warp-store = 8 runs of 16B
        #pragma unroll
        for (int p = threadIdx.x; p < 512; p += 128) {
            int c  = p >> 2;
            int dj = p & 3;
            dst[(size_t)c * NBINS + dj] = s[dj * SPITCH + c];
        }
    } else {
        // last quad: only bin 48 (wrp 0)
        int c = threadIdx.x;           // 0..127
        dst[(size_t)c * NBINS] = s[0 * SPITCH + c];
    }
}

extern "C" void kernel_launch(void* const* d_in, const int* in_sizes, int n_in,
                              void* d_out, int out_size)
{
    const float* feat = (const float*)d_in[0];
    const float* rois = (const float*)d_in[1];
    float* out = (float*)d_out;

    dim3 tgrid((HWSZ + 31) / 32, CCH / 32, BB);
    transpose_kernel<<<tgrid, 256>>>(feat);

    prep_kernel<<<(128 * NBINS + 255) / 256, 256>>>(rois);

    roi_pool_kernel<<<dim3(26, 128), 128>>>(out);
}